// round 6
// baseline (speedup 1.0000x reference)
#include <cuda_runtime.h>
#include <cuda_fp16.h>
#include <cstdint>

#define NQ 4096
#define NK 8192
#define DIM 1024

// ---------------------------------------------------------------------------
// Scratch (device globals; no allocation in kernel_launch)
// ---------------------------------------------------------------------------
__device__ int8_t g_Qi[(size_t)NQ * DIM];     //  4 MB int8 Q (per-row scaled)
__device__ int8_t g_Ki[(size_t)NK * DIM];     //  8 MB int8 K (per-row scaled)
__device__ __half g_Vt[(size_t)DIM * NK];     // 16 MB fp16 V^T [n][k]
__device__ __half g_R [(size_t)NQ * NK];      // 64 MB fp16 R = exp(cos)-1
__device__ float  g_qmul[NQ];                 // qninv * qabsmax / 127
__device__ float  g_kmul[NK];                 // kninv * kabsmax / 127
__device__ float  g_rsum[NQ];
__device__ float  g_colsum[DIM];
__device__ float  g_colpart[128][DIM];
__device__ float  g_rpart[NK / 128][NQ];      // per-n-tile row partials (GEMM1)

// ---------------------------------------------------------------------------
// PTX helpers (plain sm_103-compatible: mma.sync / ldmatrix / cp.async)
// ---------------------------------------------------------------------------
__device__ __forceinline__ uint32_t smem_u32(const void* p) {
    uint32_t a;
    asm("{ .reg .u64 t; cvta.to.shared.u64 t, %1; cvt.u32.u64 %0, t; }"
        : "=r"(a) : "l"(p));
    return a;
}
__device__ __forceinline__ void cp16(uint32_t dst, const void* src) {
    asm volatile("cp.async.cg.shared.global [%0], [%1], 16;" :: "r"(dst), "l"(src));
}
#define CP_COMMIT() asm volatile("cp.async.commit_group;" ::: "memory")
#define CP_WAIT(N)  asm volatile("cp.async.wait_group %0;" :: "n"(N) : "memory")

__device__ __forceinline__ void ldsm_x4(uint32_t (&r)[4], uint32_t addr) {
    asm volatile("ldmatrix.sync.aligned.m8n8.x4.shared.b16 {%0,%1,%2,%3}, [%4];"
        : "=r"(r[0]), "=r"(r[1]), "=r"(r[2]), "=r"(r[3]) : "r"(addr));
}
__device__ __forceinline__ void mma16816(float (&d)[4], const uint32_t (&a)[4],
                                         uint32_t b0, uint32_t b1) {
    asm volatile("mma.sync.aligned.m16n8k16.row.col.f32.f16.f16.f32 "
        "{%0,%1,%2,%3}, {%4,%5,%6,%7}, {%8,%9}, {%0,%1,%2,%3};"
        : "+f"(d[0]), "+f"(d[1]), "+f"(d[2]), "+f"(d[3])
        : "r"(a[0]), "r"(a[1]), "r"(a[2]), "r"(a[3]), "r"(b0), "r"(b1));
}
__device__ __forceinline__ void mma16832s8(int (&d)[4], const uint32_t (&a)[4],
                                           uint32_t b0, uint32_t b1) {
    asm volatile("mma.sync.aligned.m16n8k32.row.col.s32.s8.s8.s32 "
        "{%0,%1,%2,%3}, {%4,%5,%6,%7}, {%8,%9}, {%0,%1,%2,%3};"
        : "+r"(d[0]), "+r"(d[1]), "+r"(d[2]), "+r"(d[3])
        : "r"(a[0]), "r"(a[1]), "r"(a[2]), "r"(a[3]), "r"(b0), "r"(b1));
}

// ---------------------------------------------------------------------------
// Aux kernels
// ---------------------------------------------------------------------------
// Per-row int8 quantization + combined multiplier (1/|x|) * (absmax/127).
__global__ void quantize_row_kernel(const float* __restrict__ X,
                                    int8_t* __restrict__ Xi,
                                    float* __restrict__ mul) {
    int row  = blockIdx.x * 8 + (threadIdx.x >> 5);
    int lane = threadIdx.x & 31;
    const float4* xp = (const float4*)(X + (size_t)row * DIM);
    float4 v[8];
    float ss = 0.f, mx = 0.f;
#pragma unroll
    for (int i = 0; i < 8; i++) {
        v[i] = xp[lane + 32 * i];
        ss += v[i].x * v[i].x + v[i].y * v[i].y + v[i].z * v[i].z + v[i].w * v[i].w;
        mx = fmaxf(mx, fmaxf(fmaxf(fabsf(v[i].x), fabsf(v[i].y)),
                             fmaxf(fabsf(v[i].z), fabsf(v[i].w))));
    }
#pragma unroll
    for (int o = 16; o > 0; o >>= 1) {
        ss += __shfl_xor_sync(0xffffffffu, ss, o);
        mx = fmaxf(mx, __shfl_xor_sync(0xffffffffu, mx, o));
    }
    float s = 127.f / mx;
    char4* op = (char4*)(Xi + (size_t)row * DIM);
#pragma unroll
    for (int i = 0; i < 8; i++) {
        char4 c;
        c.x = (char)__float2int_rn(v[i].x * s);
        c.y = (char)__float2int_rn(v[i].y * s);
        c.z = (char)__float2int_rn(v[i].z * s);
        c.w = (char)__float2int_rn(v[i].w * s);
        op[lane + 32 * i] = c;
    }
    if (lane == 0) mul[row] = rsqrtf(ss) * mx * (1.f / 127.f);
}

__global__ void transpose_v_kernel(const float* __restrict__ V) {
    __shared__ float tile[32][33];
    int n0 = blockIdx.x * 32, k0 = blockIdx.y * 32;
    int tx = threadIdx.x, ty = threadIdx.y;           // 32 x 8
#pragma unroll
    for (int i = 0; i < 4; i++)
        tile[ty + 8 * i][tx] = V[(size_t)(k0 + ty + 8 * i) * DIM + n0 + tx];
    __syncthreads();
#pragma unroll
    for (int i = 0; i < 4; i++)
        g_Vt[(size_t)(n0 + ty + 8 * i) * NK + k0 + tx] = __float2half(tile[tx][ty + 8 * i]);
}

__global__ void colsum_part_kernel(const float* __restrict__ V) {
    int n = blockIdx.x * 256 + threadIdx.x;
    int kbase = blockIdx.y * 64;
    float s = 0.f;
#pragma unroll 8
    for (int k = 0; k < 64; k++) s += V[(size_t)(kbase + k) * DIM + n];
    g_colpart[blockIdx.y][n] = s;
}
__global__ void colsum_fin_kernel() {
    int n = blockIdx.x * 256 + threadIdx.x;
    float s = 0.f;
#pragma unroll
    for (int j = 0; j < 128; j++) s += g_colpart[j][n];
    g_colsum[n] = s;
}
__global__ void rowsum_fin_kernel() {
    int m = blockIdx.x * 256 + threadIdx.x;
    float s = (float)NK;
#pragma unroll
    for (int j = 0; j < NK / 128; j++) s += g_rpart[j][m];
    g_rsum[m] = s;
}

// ---------------------------------------------------------------------------
// Shared tiling constants (identical byte layout for int8/fp16 kernels)
// 128x128 tile, rows of 64 bytes (BK=64 int8 / BK=32 halves), pitch 80 bytes.
// ---------------------------------------------------------------------------
#define BM 128
#define BN 128
#define STAGES 3
#define RPITCH 80
#define ST_A_BYTES (BM * RPITCH)               // 10240
#define ST_BYTES   (2 * ST_A_BYTES)            // 20480 (A + B)
#define SMEM_BYTES (STAGES * ST_BYTES + 1024)  // 62464

// ---------------------------------------------------------------------------
// GEMM1 (int8 IMMA): R = exp(dot_i32 * qmul[m] * kmul[n]) - 1 -> g_R (fp16)
// plus fused per-CTA row sums -> g_rpart.  A=Qi[m][k], B=Ki[n][k], BK=64.
// ---------------------------------------------------------------------------
__global__ __launch_bounds__(256, 2) void igemm_exp_kernel(
    const int8_t* __restrict__ A, const int8_t* __restrict__ B) {
    extern __shared__ char smem[];
    const uint32_t sbase = smem_u32(smem);
    const int t = threadIdx.x;
    const int m0 = blockIdx.y * BM, n0 = blockIdx.x * BN;
    const int lane = t & 31, w = t >> 5;
    const int wm = w >> 1, wn = w & 1;          // 4 x 2 warps; warp tile 32m x 64n
    const int lrow = lane & 15, lcol = (lane >> 4) * 16;

    auto load_stage = [&](int ci, int st) {
        uint32_t sa = sbase + st * ST_BYTES;
        uint32_t sb = sa + ST_A_BYTES;
        int k0 = ci * 64;
#pragma unroll
        for (int j = 0; j < 2; j++) {
            int idx = t + 256 * j;              // 0..511
            int r = idx >> 2, c = idx & 3;      // 128 rows x 4 x 16B
            cp16(sa + r * RPITCH + c * 16, A + (size_t)(m0 + r) * DIM + k0 + c * 16);
            cp16(sb + r * RPITCH + c * 16, B + (size_t)(n0 + r) * DIM + k0 + c * 16);
        }
    };

    int acc[2][8][4] = {};

    const int KT = DIM / 64;                    // 16
    load_stage(0, 0); CP_COMMIT();
    load_stage(1, 1); CP_COMMIT();

    for (int i = 0; i < KT; i++) {
        CP_WAIT(1);
        __syncthreads();
        if (i + 2 < KT) load_stage(i + 2, (i + 2) % STAGES);
        CP_COMMIT();

        uint32_t sa = sbase + (i % STAGES) * ST_BYTES;
        uint32_t sb = sa + ST_A_BYTES;

#pragma unroll
        for (int kk = 0; kk < 2; kk++) {        // two 32-byte k-halves
            uint32_t a[2][4], bf[4][4];
#pragma unroll
            for (int mi = 0; mi < 2; mi++) {
                int row = wm * 32 + mi * 16 + lrow;
                ldsm_x4(a[mi], sa + row * RPITCH + kk * 32 + lcol);
            }
#pragma unroll
            for (int ni = 0; ni < 4; ni++) {
                int row = wn * 64 + ni * 16 + lrow;
                ldsm_x4(bf[ni], sb + row * RPITCH + kk * 32 + lcol);
            }
#pragma unroll
            for (int mi = 0; mi < 2; mi++)
#pragma unroll
                for (int ni = 0; ni < 4; ni++) {
                    mma16832s8(acc[mi][2 * ni],     a[mi], bf[ni][0], bf[ni][2]);
                    mma16832s8(acc[mi][2 * ni + 1], a[mi], bf[ni][1], bf[ni][3]);
                }
        }
    }

    // ---- Epilogue: scale, exp-1, store fp16 R, fused row partial sums ----
    const int g = lane >> 2, q = lane & 3;
    const int rbase = m0 + wm * 32;
    const int cbase = n0 + wn * 64;

    float* rp_s = (float*)(smem + STAGES * ST_BYTES);   // [2][128]
    float rs[2][2] = {};
    float kn[8][2];
#pragma unroll
    for (int nj = 0; nj < 8; nj++) {
        int c = cbase + nj * 8 + q * 2;
        kn[nj][0] = g_kmul[c]; kn[nj][1] = g_kmul[c + 1];
    }
#pragma unroll
    for (int mi = 0; mi < 2; mi++) {
        int r0 = rbase + mi * 16 + g;
        float qi0 = g_qmul[r0], qi1 = g_qmul[r0 + 8];
        __half2* d0 = (__half2*)(g_R + (size_t)r0 * NK);
        __half2* d1 = (__half2*)(g_R + (size_t)(r0 + 8) * NK);
#pragma unroll
        for (int nj = 0; nj < 8; nj++) {
            int c = cbase + nj * 8 + q * 2;
            float e00 = __expf((float)acc[mi][nj][0] * qi0 * kn[nj][0]) - 1.f;
            float e01 = __expf((float)acc[mi][nj][1] * qi0 * kn[nj][1]) - 1.f;
            float e10 = __expf((float)acc[mi][nj][2] * qi1 * kn[nj][0]) - 1.f;
            float e11 = __expf((float)acc[mi][nj][3] * qi1 * kn[nj][1]) - 1.f;
            rs[mi][0] += e00 + e01;
            rs[mi][1] += e10 + e11;
            d0[c >> 1] = __floats2half2_rn(e00, e01);
            d1[c >> 1] = __floats2half2_rn(e10, e11);
        }
    }
#pragma unroll
    for (int mi = 0; mi < 2; mi++)
#pragma unroll
        for (int h = 0; h < 2; h++) {
            float v = rs[mi][h];
            v += __shfl_xor_sync(0xffffffffu, v, 1);
            v += __shfl_xor_sync(0xffffffffu, v, 2);
            rs[mi][h] = v;
        }
    if (q == 0) {
#pragma unroll
        for (int mi = 0; mi < 2; mi++)
#pragma unroll
            for (int h = 0; h < 2; h++)
                rp_s[wn * 128 + wm * 32 + mi * 16 + h * 8 + g] = rs[mi][h];
    }
    __syncthreads();
    if (t < 128)
        g_rpart[blockIdx.x][m0 + t] = rp_s[t] + rp_s[128 + t];
}

// ---------------------------------------------------------------------------
// GEMM2 (fp16 HMMA): out = (R . V + colsumV) / rsum.  A=R[m][k], B=Vt[n][k].
// BK=32 halves (64 bytes). Unchanged from round 5 (proven config).
// ---------------------------------------------------------------------------
__global__ __launch_bounds__(256, 2) void hgemm_out_kernel(
    const __half* __restrict__ A, const __half* __restrict__ B,
    float* __restrict__ Cout) {
    extern __shared__ char smem[];
    const uint32_t sbase = smem_u32(smem);
    const int t = threadIdx.x;
    const int m0 = blockIdx.y * BM, n0 = blockIdx.x * BN;
    const int lane = t & 31, w = t >> 5;
    const int wm = w >> 1, wn = w & 1;
    const int lrow = lane & 15, lcol = (lane >> 4) * 16;

    auto load_stage = [&](int ci, int st) {
        uint32_t sa = sbase + st * ST_BYTES;
        uint32_t sb = sa + ST_A_BYTES;
        int k0 = ci * 32;
#pragma unroll
        for (int j = 0; j < 2; j++) {
            int idx = t + 256 * j;
            int r = idx >> 2, c = idx & 3;
            cp16(sa + r * RPITCH + c * 16, A + (size_t)(m0 + r) * NK + k0 + c * 8);
            cp16(sb + r * RPITCH + c * 16, B + (size_t)(n0 + r) * NK + k0 + c * 8);
        }
    };

    float acc[2][8][4] = {};

    const int KT = NK / 32;                     // 256
    load_stage(0, 0); CP_COMMIT();
    load_stage(1, 1); CP_COMMIT();

    for (int i = 0; i < KT; i++) {
        CP_WAIT(1);
        __syncthreads();
        if (i + 2 < KT) load_stage(i + 2, (i + 2) % STAGES);
        CP_COMMIT();

        uint32_t sa = sbase + (i % STAGES) * ST_BYTES;
        uint32_t sb = sa + ST_A_BYTES;

#pragma unroll
        for (int kk = 0; kk < 2; kk++) {
            uint32_t a[2][4], bf[4][4];
#pragma unroll
            for (int mi = 0; mi < 2; mi++) {
                int row = wm * 32 + mi * 16 + lrow;
                ldsm_x4(a[mi], sa + row * RPITCH + kk * 32 + lcol);
            }
#pragma unroll
            for (int ni = 0; ni < 4; ni++) {
                int row = wn * 64 + ni * 16 + lrow;
                ldsm_x4(bf[ni], sb + row * RPITCH + kk * 32 + lcol);
            }
#pragma unroll
            for (int mi = 0; mi < 2; mi++)
#pragma unroll
                for (int ni = 0; ni < 4; ni++) {
                    mma16816(acc[mi][2 * ni],     a[mi], bf[ni][0], bf[ni][2]);
                    mma16816(acc[mi][2 * ni + 1], a[mi], bf[ni][1], bf[ni][3]);
                }
        }
    }

    const int g = lane >> 2, q = lane & 3;
    const int rbase = m0 + wm * 32;
    const int cbase = n0 + wn * 64;
#pragma unroll
    for (int mi = 0; mi < 2; mi++) {
        int r0 = rbase + mi * 16 + g;
        float ri0 = 1.0f / g_rsum[r0], ri1 = 1.0f / g_rsum[r0 + 8];
        float* d0 = Cout + (size_t)r0 * DIM;
        float* d1 = Cout + (size_t)(r0 + 8) * DIM;
#pragma unroll
        for (int nj = 0; nj < 8; nj++) {
            int c = cbase + nj * 8 + q * 2;
            float cs0 = g_colsum[c], cs1 = g_colsum[c + 1];
            *(float2*)(d0 + c) = make_float2((acc[mi][nj][0] + cs0) * ri0,
                                             (acc[mi][nj][1] + cs1) * ri0);
            *(float2*)(d1 + c) = make_float2((acc[mi][nj][2] + cs0) * ri1,
                                             (acc[mi][nj][3] + cs1) * ri1);
        }
    }
}

// ---------------------------------------------------------------------------
// Launch
// ---------------------------------------------------------------------------
extern "C" void kernel_launch(void* const* d_in, const int* in_sizes, int n_in,
                              void* d_out, int out_size) {
    const float* Q = (const float*)d_in[0];   // [4096, 1024]
    const float* K = (const float*)d_in[1];   // [8192, 1024] (keys == values)
    float* out = (float*)d_out;               // [4096, 1024]
    (void)in_sizes; (void)n_in; (void)out_size;

    void *Qi, *Ki, *Vt, *R, *qm, *km;
    cudaGetSymbolAddress(&Qi, g_Qi);
    cudaGetSymbolAddress(&Ki, g_Ki);
    cudaGetSymbolAddress(&Vt, g_Vt);
    cudaGetSymbolAddress(&R,  g_R);
    cudaGetSymbolAddress(&qm, g_qmul);
    cudaGetSymbolAddress(&km, g_kmul);

    cudaFuncSetAttribute(igemm_exp_kernel, cudaFuncAttributeMaxDynamicSharedMemorySize, SMEM_BYTES);
    cudaFuncSetAttribute(hgemm_out_kernel, cudaFuncAttributeMaxDynamicSharedMemorySize, SMEM_BYTES);

    quantize_row_kernel<<<NQ / 8, 256>>>(Q, (int8_t*)Qi, (float*)qm);
    quantize_row_kernel<<<NK / 8, 256>>>(K, (int8_t*)Ki, (float*)km);
    transpose_v_kernel<<<dim3(DIM / 32, NK / 32), dim3(32, 8)>>>(K);
    colsum_part_kernel<<<dim3(DIM / 256, 128), 256>>>(K);
    colsum_fin_kernel<<<DIM / 256, 256>>>();

    // GEMM1 (int8): R = exp(cos(Q,K)) - 1, fused row partials
    igemm_exp_kernel<<<dim3(NK / BN, NQ / BM), 256, SMEM_BYTES>>>(
        (const int8_t*)Qi, (const int8_t*)Ki);

    rowsum_fin_kernel<<<NQ / 256, 256>>>();

    // GEMM2 (fp16): out = (R . V + colsumV) / rsum
    hgemm_out_kernel<<<dim3(DIM / BN, NQ / BM), 256, SMEM_BYTES>>>(
        (const __half*)R, (const __half*)Vt, out);
}

// round 7
// speedup vs baseline: 1.0658x; 1.0658x over previous
#include <cuda_runtime.h>
#include <cuda_fp16.h>
#include <cstdint>

#define NQ 4096
#define NK 8192
#define DIM 1024

// ---------------------------------------------------------------------------
// Scratch (device globals; no allocation in kernel_launch)
// ---------------------------------------------------------------------------
__device__ __half g_Qh[(size_t)NQ * DIM];     //  8 MB fp16 Q
__device__ __half g_Kh[(size_t)NK * DIM];     // 16 MB fp16 K (K-major)
__device__ __half g_Vt[(size_t)DIM * NK];     // 16 MB fp16 V^T [n][k]
__device__ __half g_R [(size_t)NQ * NK];      // 64 MB fp16 R = exp(cos)-1
__device__ float  g_qninv[NQ];
__device__ float  g_kninv[NK];
__device__ float  g_rsum[NQ];
__device__ float  g_colsum[DIM];
__device__ float  g_colpart[128][DIM];
__device__ float  g_rpart[NK / 128][NQ];      // per-n-tile row partials (GEMM1)

// ---------------------------------------------------------------------------
// PTX helpers (plain sm_103-compatible: mma.sync / ldmatrix / cp.async)
// ---------------------------------------------------------------------------
__device__ __forceinline__ uint32_t smem_u32(const void* p) {
    uint32_t a;
    asm("{ .reg .u64 t; cvta.to.shared.u64 t, %1; cvt.u32.u64 %0, t; }"
        : "=r"(a) : "l"(p));
    return a;
}
__device__ __forceinline__ void cp16(uint32_t dst, const void* src) {
    asm volatile("cp.async.cg.shared.global [%0], [%1], 16;" :: "r"(dst), "l"(src));
}
#define CP_COMMIT() asm volatile("cp.async.commit_group;" ::: "memory")
#define CP_WAIT(N)  asm volatile("cp.async.wait_group %0;" :: "n"(N) : "memory")

__device__ __forceinline__ void ldsm_x4(uint32_t (&r)[4], uint32_t addr) {
    asm volatile("ldmatrix.sync.aligned.m8n8.x4.shared.b16 {%0,%1,%2,%3}, [%4];"
        : "=r"(r[0]), "=r"(r[1]), "=r"(r[2]), "=r"(r[3]) : "r"(addr));
}

// fp16-accumulate HMMA: d(f16x2 x2) = a*b + c ; used with c = 0, then the
// result is promoted to the fp32 accumulators (one f16 rounding per 16-dot).
__device__ __forceinline__ void mma16816h(uint32_t (&d)[2], const uint32_t (&a)[4],
                                          uint32_t b0, uint32_t b1, uint32_t z) {
    asm volatile("mma.sync.aligned.m16n8k16.row.col.f16.f16.f16.f16 "
        "{%0,%1}, {%2,%3,%4,%5}, {%6,%7}, {%8,%9};"
        : "=r"(d[0]), "=r"(d[1])
        : "r"(a[0]), "r"(a[1]), "r"(a[2]), "r"(a[3]), "r"(b0), "r"(b1),
          "r"(z), "r"(z));
}
__device__ __forceinline__ void mma_promote(float (&acc)[4], const uint32_t (&a)[4],
                                            uint32_t b0, uint32_t b1, uint32_t z) {
    uint32_t d[2];
    mma16816h(d, a, b0, b1, z);
    float2 lo = __half22float2(*(__half2*)&d[0]);
    float2 hi = __half22float2(*(__half2*)&d[1]);
    acc[0] += lo.x; acc[1] += lo.y; acc[2] += hi.x; acc[3] += hi.y;
}

// ---------------------------------------------------------------------------
// Aux kernels
// ---------------------------------------------------------------------------
__global__ void convert_norm_kernel(const float* __restrict__ X,
                                    __half* __restrict__ Xh,
                                    float* __restrict__ ninv) {
    int row  = blockIdx.x * 8 + (threadIdx.x >> 5);
    int lane = threadIdx.x & 31;
    const float4* xp = (const float4*)(X + (size_t)row * DIM);
    __half2* op = (__half2*)(Xh + (size_t)row * DIM);
    float s = 0.f;
#pragma unroll
    for (int i = 0; i < 8; i++) {
        float4 v = xp[lane + 32 * i];
        s += v.x * v.x + v.y * v.y + v.z * v.z + v.w * v.w;
        op[(lane + 32 * i) * 2]     = __floats2half2_rn(v.x, v.y);
        op[(lane + 32 * i) * 2 + 1] = __floats2half2_rn(v.z, v.w);
    }
#pragma unroll
    for (int o = 16; o > 0; o >>= 1) s += __shfl_xor_sync(0xffffffffu, s, o);
    if (lane == 0) ninv[row] = rsqrtf(s);
}

__global__ void transpose_v_kernel(const float* __restrict__ V) {
    __shared__ float tile[32][33];
    int n0 = blockIdx.x * 32, k0 = blockIdx.y * 32;
    int tx = threadIdx.x, ty = threadIdx.y;           // 32 x 8
#pragma unroll
    for (int i = 0; i < 4; i++)
        tile[ty + 8 * i][tx] = V[(size_t)(k0 + ty + 8 * i) * DIM + n0 + tx];
    __syncthreads();
#pragma unroll
    for (int i = 0; i < 4; i++)
        g_Vt[(size_t)(n0 + ty + 8 * i) * NK + k0 + tx] = __float2half(tile[tx][ty + 8 * i]);
}

__global__ void colsum_part_kernel(const float* __restrict__ V) {
    int n = blockIdx.x * 256 + threadIdx.x;
    int kbase = blockIdx.y * 64;
    float s = 0.f;
#pragma unroll 8
    for (int k = 0; k < 64; k++) s += V[(size_t)(kbase + k) * DIM + n];
    g_colpart[blockIdx.y][n] = s;
}
__global__ void colsum_fin_kernel() {
    int n = blockIdx.x * 256 + threadIdx.x;
    float s = 0.f;
#pragma unroll
    for (int j = 0; j < 128; j++) s += g_colpart[j][n];
    g_colsum[n] = s;
}
__global__ void rowsum_fin_kernel() {
    int m = blockIdx.x * 256 + threadIdx.x;
    float s = (float)NK;
#pragma unroll
    for (int j = 0; j < NK / 128; j++) s += g_rpart[j][m];
    g_rsum[m] = s;
}

// ---------------------------------------------------------------------------
// HMMA fp16 GEMM: 128x128x32 tile, 256 threads, 3-stage cp.async, 2 CTA/SM.
// Warp grid 4(m) x 2(n); warp tile 32m x 64n. fp16-acc MMA + per-MMA fp32
// promotion (probe: is f16-acc rt half of f32-acc rt on this chip?).
//   MODE 0: A=Qh[m][k], B=Kh[n][k]; epi r=exp(acc*qninv*kninv)-1 -> g_R,
//           fused per-CTA row sums -> g_rpart[blockIdx.x][m]
//   MODE 1: A=R[m][k],  B=Vt[n][k]; epi (acc + colsum[n]) / rsum[m] -> Cout
// ---------------------------------------------------------------------------
#define BM 128
#define BN 128
#define BK 32
#define STAGES 3
#define APITCH 40                              // halves per row (pad 32->40)
#define ST_A_BYTES (BM * APITCH * 2)           // 10240
#define ST_BYTES   (2 * ST_A_BYTES)            // 20480 (A + B)
#define SMEM_BYTES (STAGES * ST_BYTES + 1024)  // 62464 (incl. rp_s scratch)

template <int MODE>
__global__ __launch_bounds__(256, 2) void hgemm_kernel(
    const __half* __restrict__ A, const __half* __restrict__ B,
    int lda, int ldb, int kdim, float* __restrict__ Cout) {
    extern __shared__ char smem[];
    const uint32_t sbase = smem_u32(smem);
    const int t = threadIdx.x;
    const int m0 = blockIdx.y * BM, n0 = blockIdx.x * BN;
    const int lane = t & 31, w = t >> 5;
    const int wm = w >> 1, wn = w & 1;          // 4 x 2 warp grid; tile 32m x 64n
    const int lrow = lane & 15, lcol = (lane >> 4) * 16;
    const uint32_t z = 0;                       // f16x2 zero for mma c-operand

    auto load_stage = [&](int ci, int st) {
        uint32_t sa = sbase + st * ST_BYTES;
        uint32_t sb = sa + ST_A_BYTES;
        int k0 = ci * BK;
#pragma unroll
        for (int j = 0; j < 2; j++) {
            int idx = t + 256 * j;              // 0..511
            int r = idx >> 2, c = idx & 3;      // 128 rows x 4 chunks(16B)
            cp16(sa + r * (APITCH * 2) + c * 16,
                 A + (size_t)(m0 + r) * lda + k0 + c * 8);
            cp16(sb + r * (APITCH * 2) + c * 16,
                 B + (size_t)(n0 + r) * ldb + k0 + c * 8);
        }
    };

    float acc[2][8][4] = {};

    const int KT = kdim / BK;
    load_stage(0, 0); CP_COMMIT();
    load_stage(1, 1); CP_COMMIT();

    for (int i = 0; i < KT; i++) {
        CP_WAIT(1);
        __syncthreads();
        if (i + 2 < KT) load_stage(i + 2, (i + 2) % STAGES);
        CP_COMMIT();

        uint32_t sa = sbase + (i % STAGES) * ST_BYTES;
        uint32_t sb = sa + ST_A_BYTES;

#pragma unroll
        for (int kk = 0; kk < 2; kk++) {
            uint32_t a[2][4], bf[4][4];
#pragma unroll
            for (int mi = 0; mi < 2; mi++) {
                int row = wm * 32 + mi * 16 + lrow;
                ldsm_x4(a[mi], sa + row * (APITCH * 2) + kk * 32 + lcol);
            }
#pragma unroll
            for (int ni = 0; ni < 4; ni++) {
                int row = wn * 64 + ni * 16 + lrow;
                ldsm_x4(bf[ni], sb + row * (APITCH * 2) + kk * 32 + lcol);
            }
#pragma unroll
            for (int mi = 0; mi < 2; mi++)
#pragma unroll
                for (int ni = 0; ni < 4; ni++) {
                    mma_promote(acc[mi][2 * ni],     a[mi], bf[ni][0], bf[ni][2], z);
                    mma_promote(acc[mi][2 * ni + 1], a[mi], bf[ni][1], bf[ni][3], z);
                }
        }
    }

    // ---- Epilogue ----
    const int g = lane >> 2, q = lane & 3;
    const int rbase = m0 + wm * 32;
    const int cbase = n0 + wn * 64;

    if (MODE == 0) {
        float* rp_s = (float*)(smem + STAGES * ST_BYTES);   // [2][128]
        float rs[2][2] = {};
        float kn[8][2];
#pragma unroll
        for (int nj = 0; nj < 8; nj++) {
            int c = cbase + nj * 8 + q * 2;
            kn[nj][0] = g_kninv[c]; kn[nj][1] = g_kninv[c + 1];
        }
#pragma unroll
        for (int mi = 0; mi < 2; mi++) {
            int r0 = rbase + mi * 16 + g;
            float qi0 = g_qninv[r0], qi1 = g_qninv[r0 + 8];
            __half2* d0 = (__half2*)(g_R + (size_t)r0 * NK);
            __half2* d1 = (__half2*)(g_R + (size_t)(r0 + 8) * NK);
#pragma unroll
            for (int nj = 0; nj < 8; nj++) {
                int c = cbase + nj * 8 + q * 2;
                float e00 = __expf(acc[mi][nj][0] * qi0 * kn[nj][0]) - 1.f;
                float e01 = __expf(acc[mi][nj][1] * qi0 * kn[nj][1]) - 1.f;
                float e10 = __expf(acc[mi][nj][2] * qi1 * kn[nj][0]) - 1.f;
                float e11 = __expf(acc[mi][nj][3] * qi1 * kn[nj][1]) - 1.f;
                rs[mi][0] += e00 + e01;
                rs[mi][1] += e10 + e11;
                d0[c >> 1] = __floats2half2_rn(e00, e01);
                d1[c >> 1] = __floats2half2_rn(e10, e11);
            }
        }
        // reduce over the 4 q-lanes sharing each row
#pragma unroll
        for (int mi = 0; mi < 2; mi++)
#pragma unroll
            for (int h = 0; h < 2; h++) {
                float v = rs[mi][h];
                v += __shfl_xor_sync(0xffffffffu, v, 1);
                v += __shfl_xor_sync(0xffffffffu, v, 2);
                rs[mi][h] = v;
            }
        if (q == 0) {
#pragma unroll
            for (int mi = 0; mi < 2; mi++)
#pragma unroll
                for (int h = 0; h < 2; h++)
                    rp_s[wn * 128 + wm * 32 + mi * 16 + h * 8 + g] = rs[mi][h];
        }
        __syncthreads();
        if (t < 128)
            g_rpart[blockIdx.x][m0 + t] = rp_s[t] + rp_s[128 + t];
    } else {
#pragma unroll
        for (int mi = 0; mi < 2; mi++) {
            int r0 = rbase + mi * 16 + g;
            float ri0 = 1.0f / g_rsum[r0], ri1 = 1.0f / g_rsum[r0 + 8];
            float* d0 = Cout + (size_t)r0 * DIM;
            float* d1 = Cout + (size_t)(r0 + 8) * DIM;
#pragma unroll
            for (int nj = 0; nj < 8; nj++) {
                int c = cbase + nj * 8 + q * 2;
                float cs0 = g_colsum[c], cs1 = g_colsum[c + 1];
                *(float2*)(d0 + c) = make_float2((acc[mi][nj][0] + cs0) * ri0,
                                                 (acc[mi][nj][1] + cs1) * ri0);
                *(float2*)(d1 + c) = make_float2((acc[mi][nj][2] + cs0) * ri1,
                                                 (acc[mi][nj][3] + cs1) * ri1);
            }
        }
    }
}

// ---------------------------------------------------------------------------
// Launch
// ---------------------------------------------------------------------------
extern "C" void kernel_launch(void* const* d_in, const int* in_sizes, int n_in,
                              void* d_out, int out_size) {
    const float* Q = (const float*)d_in[0];   // [4096, 1024]
    const float* K = (const float*)d_in[1];   // [8192, 1024] (keys == values)
    float* out = (float*)d_out;               // [4096, 1024]
    (void)in_sizes; (void)n_in; (void)out_size;

    void *Qh, *Kh, *Vt, *R, *qn, *kn;
    cudaGetSymbolAddress(&Qh, g_Qh);
    cudaGetSymbolAddress(&Kh, g_Kh);
    cudaGetSymbolAddress(&Vt, g_Vt);
    cudaGetSymbolAddress(&R,  g_R);
    cudaGetSymbolAddress(&qn, g_qninv);
    cudaGetSymbolAddress(&kn, g_kninv);

    cudaFuncSetAttribute(hgemm_kernel<0>, cudaFuncAttributeMaxDynamicSharedMemorySize, SMEM_BYTES);
    cudaFuncSetAttribute(hgemm_kernel<1>, cudaFuncAttributeMaxDynamicSharedMemorySize, SMEM_BYTES);

    convert_norm_kernel<<<NQ / 8, 256>>>(Q, (__half*)Qh, (float*)qn);
    convert_norm_kernel<<<NK / 8, 256>>>(K, (__half*)Kh, (float*)kn);
    transpose_v_kernel<<<dim3(DIM / 32, NK / 32), dim3(32, 8)>>>(K);
    colsum_part_kernel<<<dim3(DIM / 256, 128), 256>>>(K);
    colsum_fin_kernel<<<DIM / 256, 256>>>();

    // GEMM1: R = exp(cos(Q,K)) - 1   [4096 x 8192] (+ fused row partials)
    hgemm_kernel<0><<<dim3(NK / BN, NQ / BM), 256, SMEM_BYTES>>>(
        (const __half*)Qh, (const __half*)Kh, DIM, DIM, DIM, nullptr);

    rowsum_fin_kernel<<<NQ / 256, 256>>>();

    // GEMM2: out = (R . V + colsumV) / rsum   [4096 x 1024]
    hgemm_kernel<1><<<dim3(DIM / BN, NQ / BM), 256, SMEM_BYTES>>>(
        (const __half*)R, (const __half*)Vt, NK, NK, NK, out);
}

// round 8
// speedup vs baseline: 1.3266x; 1.2447x over previous
#include <cuda_runtime.h>
#include <cuda_fp16.h>
#include <cstdint>

#define NQ 4096
#define NK 8192
#define DIM 1024

// ---------------------------------------------------------------------------
// Scratch (device globals; no allocation in kernel_launch)
// ---------------------------------------------------------------------------
__device__ __half g_Qh[(size_t)NQ * DIM];     //  8 MB fp16 Q
__device__ __half g_Kh[(size_t)NK * DIM];     // 16 MB fp16 K (K-major)
__device__ __half g_Vt[(size_t)DIM * NK];     // 16 MB fp16 V^T [n][k]
__device__ __half g_R [(size_t)NQ * NK];      // 64 MB fp16 R = exp(cos)-1
__device__ float  g_qninv[NQ];
__device__ float  g_kninv[NK];
__device__ float  g_rsum[NQ];
__device__ float  g_colsum[DIM];
__device__ float  g_knpart[32][NK];           // per-dim-strip |k|^2 partials
__device__ float  g_colpart[256][DIM];        // per-key-strip colsum partials
__device__ float  g_rpart[NK / 128][NQ];      // per-n-tile row partials (GEMM1)

// ---------------------------------------------------------------------------
// PTX helpers (plain sm_103-compatible: mma.sync / ldmatrix / cp.async)
// ---------------------------------------------------------------------------
__device__ __forceinline__ uint32_t smem_u32(const void* p) {
    uint32_t a;
    asm("{ .reg .u64 t; cvta.to.shared.u64 t, %1; cvt.u32.u64 %0, t; }"
        : "=r"(a) : "l"(p));
    return a;
}
__device__ __forceinline__ void cp16(uint32_t dst, const void* src) {
    asm volatile("cp.async.cg.shared.global [%0], [%1], 16;" :: "r"(dst), "l"(src));
}
#define CP_COMMIT() asm volatile("cp.async.commit_group;" ::: "memory")
#define CP_WAIT(N)  asm volatile("cp.async.wait_group %0;" :: "n"(N) : "memory")

__device__ __forceinline__ void ldsm_x4(uint32_t (&r)[4], uint32_t addr) {
    asm volatile("ldmatrix.sync.aligned.m8n8.x4.shared.b16 {%0,%1,%2,%3}, [%4];"
        : "=r"(r[0]), "=r"(r[1]), "=r"(r[2]), "=r"(r[3]) : "r"(addr));
}
__device__ __forceinline__ void mma16816(float (&d)[4], const uint32_t (&a)[4],
                                         uint32_t b0, uint32_t b1) {
    asm volatile("mma.sync.aligned.m16n8k16.row.col.f32.f16.f16.f32 "
        "{%0,%1,%2,%3}, {%4,%5,%6,%7}, {%8,%9}, {%0,%1,%2,%3};"
        : "+f"(d[0]), "+f"(d[1]), "+f"(d[2]), "+f"(d[3])
        : "r"(a[0]), "r"(a[1]), "r"(a[2]), "r"(a[3]), "r"(b0), "r"(b1));
}

// ---------------------------------------------------------------------------
// Aux kernels
// ---------------------------------------------------------------------------
__global__ void convert_norm_kernel(const float* __restrict__ X,
                                    __half* __restrict__ Xh,
                                    float* __restrict__ ninv) {
    int row  = blockIdx.x * 8 + (threadIdx.x >> 5);
    int lane = threadIdx.x & 31;
    const float4* xp = (const float4*)(X + (size_t)row * DIM);
    __half2* op = (__half2*)(Xh + (size_t)row * DIM);
    float s = 0.f;
#pragma unroll
    for (int i = 0; i < 8; i++) {
        float4 v = xp[lane + 32 * i];
        s += v.x * v.x + v.y * v.y + v.z * v.z + v.w * v.w;
        op[(lane + 32 * i) * 2]     = __floats2half2_rn(v.x, v.y);
        op[(lane + 32 * i) * 2 + 1] = __floats2half2_rn(v.z, v.w);
    }
#pragma unroll
    for (int o = 16; o > 0; o >>= 1) s += __shfl_xor_sync(0xffffffffu, s, o);
    if (lane == 0) ninv[row] = rsqrtf(s);
}

// Single pass over K: emits Kh (fp16), Vt (fp16 transpose), |k|^2 strip
// partials, colsum strip partials. Block 32x8, tile 32(key) x 32(dim).
__global__ void fuse_k_kernel(const float* __restrict__ K) {
    __shared__ float tile[32][33];
    int n0 = blockIdx.x * 32;          // dim offset
    int k0 = blockIdx.y * 32;          // key offset
    int tx = threadIdx.x, ty = threadIdx.y;
#pragma unroll
    for (int i = 0; i < 4; i++) {
        int k = k0 + ty + 8 * i;
        float v = K[(size_t)k * DIM + n0 + tx];
        g_Kh[(size_t)k * DIM + n0 + tx] = __float2half(v);
        tile[ty + 8 * i][tx] = v;
    }
    __syncthreads();
#pragma unroll
    for (int i = 0; i < 4; i++)
        g_Vt[(size_t)(n0 + ty + 8 * i) * NK + k0 + tx] =
            __float2half(tile[tx][ty + 8 * i]);
    if (ty == 0) {                     // |k|^2 partial over this 32-dim strip
        float s = 0.f;
#pragma unroll
        for (int j = 0; j < 32; j++) { float v = tile[tx][j]; s += v * v; }
        g_knpart[blockIdx.x][k0 + tx] = s;
    } else if (ty == 1) {              // colsum partial over this 32-key strip
        float s = 0.f;
#pragma unroll
        for (int j = 0; j < 32; j++) s += tile[j][tx];
        g_colpart[blockIdx.y][n0 + tx] = s;
    }
}

// Finish kninv (8192) and colsum (1024) in one launch.
__global__ void kfin_kernel() {
    int gid = blockIdx.x * 256 + threadIdx.x;
    float s = 0.f;
#pragma unroll
    for (int j = 0; j < 32; j++) s += g_knpart[j][gid];
    g_kninv[gid] = rsqrtf(s);
    if (gid < DIM) {
        float c = 0.f;
        for (int j = 0; j < 256; j++) c += g_colpart[j][gid];
        g_colsum[gid] = c;
    }
}

__global__ void rowsum_fin_kernel() {
    int m = blockIdx.x * 256 + threadIdx.x;
    float s = (float)NK;
#pragma unroll
    for (int j = 0; j < NK / 128; j++) s += g_rpart[j][m];
    g_rsum[m] = s;
}

// ---------------------------------------------------------------------------
// GEMM1: 128x128x32 tile, 256 threads, 3-stage cp.async, 2 CTA/SM (proven R5).
// A=Qh[m][k], B=Kh[n][k]; epi r=exp(acc*qninv*kninv)-1 -> g_R (fp16),
// fused per-CTA row sums -> g_rpart[blockIdx.x][m].
// ---------------------------------------------------------------------------
#define BM 128
#define BN 128
#define BK 32
#define STAGES 3
#define APITCH 40                              // halves per row (pad 32->40)
#define ST_A_BYTES (BM * APITCH * 2)           // 10240
#define ST_BYTES   (2 * ST_A_BYTES)            // 20480 (A + B)
#define SMEM1_BYTES (STAGES * ST_BYTES + 1024) // 62464 (incl. rp_s scratch)

__global__ __launch_bounds__(256, 2) void hgemm1_kernel(
    const __half* __restrict__ A, const __half* __restrict__ B) {
    extern __shared__ char smem[];
    const uint32_t sbase = smem_u32(smem);
    const int t = threadIdx.x;
    const int m0 = blockIdx.y * BM, n0 = blockIdx.x * BN;
    const int lane = t & 31, w = t >> 5;
    const int wm = w >> 1, wn = w & 1;          // 4 x 2 warp grid; tile 32m x 64n
    const int lrow = lane & 15, lcol = (lane >> 4) * 16;

    auto load_stage = [&](int ci, int st) {
        uint32_t sa = sbase + st * ST_BYTES;
        uint32_t sb = sa + ST_A_BYTES;
        int k0 = ci * BK;
#pragma unroll
        for (int j = 0; j < 2; j++) {
            int idx = t + 256 * j;
            int r = idx >> 2, c = idx & 3;
            cp16(sa + r * (APITCH * 2) + c * 16,
                 A + (size_t)(m0 + r) * DIM + k0 + c * 8);
            cp16(sb + r * (APITCH * 2) + c * 16,
                 B + (size_t)(n0 + r) * DIM + k0 + c * 8);
        }
    };

    float acc[2][8][4] = {};
    const int KT = DIM / BK;
    load_stage(0, 0); CP_COMMIT();
    load_stage(1, 1); CP_COMMIT();

    for (int i = 0; i < KT; i++) {
        CP_WAIT(1);
        __syncthreads();
        if (i + 2 < KT) load_stage(i + 2, (i + 2) % STAGES);
        CP_COMMIT();

        uint32_t sa = sbase + (i % STAGES) * ST_BYTES;
        uint32_t sb = sa + ST_A_BYTES;
#pragma unroll
        for (int kk = 0; kk < 2; kk++) {
            uint32_t a[2][4], bf[4][4];
#pragma unroll
            for (int mi = 0; mi < 2; mi++) {
                int row = wm * 32 + mi * 16 + lrow;
                ldsm_x4(a[mi], sa + row * (APITCH * 2) + kk * 32 + lcol);
            }
#pragma unroll
            for (int ni = 0; ni < 4; ni++) {
                int row = wn * 64 + ni * 16 + lrow;
                ldsm_x4(bf[ni], sb + row * (APITCH * 2) + kk * 32 + lcol);
            }
#pragma unroll
            for (int mi = 0; mi < 2; mi++)
#pragma unroll
                for (int ni = 0; ni < 4; ni++) {
                    mma16816(acc[mi][2 * ni],     a[mi], bf[ni][0], bf[ni][2]);
                    mma16816(acc[mi][2 * ni + 1], a[mi], bf[ni][1], bf[ni][3]);
                }
        }
    }

    const int g = lane >> 2, q = lane & 3;
    const int rbase = m0 + wm * 32;
    const int cbase = n0 + wn * 64;

    float* rp_s = (float*)(smem + STAGES * ST_BYTES);   // [2][128]
    float rs[2][2] = {};
    float kn[8][2];
#pragma unroll
    for (int nj = 0; nj < 8; nj++) {
        int c = cbase + nj * 8 + q * 2;
        kn[nj][0] = g_kninv[c]; kn[nj][1] = g_kninv[c + 1];
    }
#pragma unroll
    for (int mi = 0; mi < 2; mi++) {
        int r0 = rbase + mi * 16 + g;
        float qi0 = g_qninv[r0], qi1 = g_qninv[r0 + 8];
        __half2* d0 = (__half2*)(g_R + (size_t)r0 * NK);
        __half2* d1 = (__half2*)(g_R + (size_t)(r0 + 8) * NK);
#pragma unroll
        for (int nj = 0; nj < 8; nj++) {
            int c = cbase + nj * 8 + q * 2;
            float e00 = __expf(acc[mi][nj][0] * qi0 * kn[nj][0]) - 1.f;
            float e01 = __expf(acc[mi][nj][1] * qi0 * kn[nj][1]) - 1.f;
            float e10 = __expf(acc[mi][nj][2] * qi1 * kn[nj][0]) - 1.f;
            float e11 = __expf(acc[mi][nj][3] * qi1 * kn[nj][1]) - 1.f;
            rs[mi][0] += e00 + e01;
            rs[mi][1] += e10 + e11;
            d0[c >> 1] = __floats2half2_rn(e00, e01);
            d1[c >> 1] = __floats2half2_rn(e10, e11);
        }
    }
#pragma unroll
    for (int mi = 0; mi < 2; mi++)
#pragma unroll
        for (int h = 0; h < 2; h++) {
            float v = rs[mi][h];
            v += __shfl_xor_sync(0xffffffffu, v, 1);
            v += __shfl_xor_sync(0xffffffffu, v, 2);
            rs[mi][h] = v;
        }
    if (q == 0) {
#pragma unroll
        for (int mi = 0; mi < 2; mi++)
#pragma unroll
            for (int h = 0; h < 2; h++)
                rp_s[wn * 128 + wm * 32 + mi * 16 + h * 8 + g] = rs[mi][h];
    }
    __syncthreads();
    if (t < 128)
        g_rpart[blockIdx.x][m0 + t] = rp_s[t] + rp_s[128 + t];
}

// ---------------------------------------------------------------------------
// GEMM2: 64(M) x 128(N) x 32(K) tile, 256 threads, 3-stage, 3 CTA/SM target.
// 512 CTAs fill all 148 SMs (vs 256 CTAs / 128 SMs before).
// Warp grid 4(m) x 2(n); warp tile 16m x 64n. A=R[m][k], B=Vt[n][k].
// epi (acc + colsum[n]) / rsum[m] -> Cout.
// ---------------------------------------------------------------------------
#define BM2 64
#define A2_BYTES (BM2 * APITCH * 2)            // 5120
#define ST2_BYTES (A2_BYTES + BN * APITCH * 2) // 15360
#define SMEM2_BYTES (STAGES * ST2_BYTES)       // 46080

__global__ __launch_bounds__(256, 3) void hgemm2_kernel(
    const __half* __restrict__ A, const __half* __restrict__ B,
    float* __restrict__ Cout) {
    extern __shared__ char smem[];
    const uint32_t sbase = smem_u32(smem);
    const int t = threadIdx.x;
    const int m0 = blockIdx.y * BM2, n0 = blockIdx.x * BN;
    const int lane = t & 31, w = t >> 5;
    const int wm = w >> 1, wn = w & 1;          // 4 x 2 warps; warp tile 16m x 64n
    const int lrow = lane & 15, lcol = (lane >> 4) * 16;

    auto load_stage = [&](int ci, int st) {
        uint32_t sa = sbase + st * ST2_BYTES;
        uint32_t sb = sa + A2_BYTES;
        int k0 = ci * BK;
        {   // A: 64 rows x 4 x 16B = 256 cp
            int r = t >> 2, c = t & 3;
            cp16(sa + r * (APITCH * 2) + c * 16,
                 A + (size_t)(m0 + r) * NK + k0 + c * 8);
        }
#pragma unroll
        for (int j = 0; j < 2; j++) {           // B: 128 rows x 4 x 16B = 512 cp
            int idx = t + 256 * j;
            int r = idx >> 2, c = idx & 3;
            cp16(sb + r * (APITCH * 2) + c * 16,
                 B + (size_t)(n0 + r) * NK + k0 + c * 8);
        }
    };

    float acc[8][4] = {};
    const int KT = NK / BK;                     // 256
    load_stage(0, 0); CP_COMMIT();
    load_stage(1, 1); CP_COMMIT();

    for (int i = 0; i < KT; i++) {
        CP_WAIT(1);
        __syncthreads();
        if (i + 2 < KT) load_stage(i + 2, (i + 2) % STAGES);
        CP_COMMIT();

        uint32_t sa = sbase + (i % STAGES) * ST2_BYTES;
        uint32_t sb = sa + A2_BYTES;
#pragma unroll
        for (int kk = 0; kk < 2; kk++) {
            uint32_t a[4], bf[4][4];
            ldsm_x4(a, sa + (wm * 16 + lrow) * (APITCH * 2) + kk * 32 + lcol);
#pragma unroll
            for (int ni = 0; ni < 4; ni++) {
                int row = wn * 64 + ni * 16 + lrow;
                ldsm_x4(bf[ni], sb + row * (APITCH * 2) + kk * 32 + lcol);
            }
#pragma unroll
            for (int ni = 0; ni < 4; ni++) {
                mma16816(acc[2 * ni],     a, bf[ni][0], bf[ni][2]);
                mma16816(acc[2 * ni + 1], a, bf[ni][1], bf[ni][3]);
            }
        }
    }

    const int g = lane >> 2, q = lane & 3;
    const int r0 = m0 + wm * 16 + g;
    const int cbase = n0 + wn * 64;
    float ri0 = 1.0f / g_rsum[r0], ri1 = 1.0f / g_rsum[r0 + 8];
    float* d0 = Cout + (size_t)r0 * DIM;
    float* d1 = Cout + (size_t)(r0 + 8) * DIM;
#pragma unroll
    for (int j = 0; j < 8; j++) {
        int c = cbase + (j >> 1) * 16 + (j & 1) * 8 + q * 2;
        float cs0 = g_colsum[c], cs1 = g_colsum[c + 1];
        *(float2*)(d0 + c) = make_float2((acc[j][0] + cs0) * ri0,
                                         (acc[j][1] + cs1) * ri0);
        *(float2*)(d1 + c) = make_float2((acc[j][2] + cs0) * ri1,
                                         (acc[j][3] + cs1) * ri1);
    }
}

// ---------------------------------------------------------------------------
// Launch
// ---------------------------------------------------------------------------
extern "C" void kernel_launch(void* const* d_in, const int* in_sizes, int n_in,
                              void* d_out, int out_size) {
    const float* Q = (const float*)d_in[0];   // [4096, 1024]
    const float* K = (const float*)d_in[1];   // [8192, 1024] (keys == values)
    float* out = (float*)d_out;               // [4096, 1024]
    (void)in_sizes; (void)n_in; (void)out_size;

    void *Qh, *Kh, *Vt, *R, *qn;
    cudaGetSymbolAddress(&Qh, g_Qh);
    cudaGetSymbolAddress(&Kh, g_Kh);
    cudaGetSymbolAddress(&Vt, g_Vt);
    cudaGetSymbolAddress(&R,  g_R);
    cudaGetSymbolAddress(&qn, g_qninv);

    cudaFuncSetAttribute(hgemm1_kernel, cudaFuncAttributeMaxDynamicSharedMemorySize, SMEM1_BYTES);
    cudaFuncSetAttribute(hgemm2_kernel, cudaFuncAttributeMaxDynamicSharedMemorySize, SMEM2_BYTES);

    convert_norm_kernel<<<NQ / 8, 256>>>(Q, (__half*)Qh, (float*)qn);
    fuse_k_kernel<<<dim3(DIM / 32, NK / 32), dim3(32, 8)>>>(K);
    kfin_kernel<<<NK / 256, 256>>>();

    // GEMM1: R = exp(cos(Q,K)) - 1   [4096 x 8192] (+ fused row partials)
    hgemm1_kernel<<<dim3(NK / BN, NQ / BM), 256, SMEM1_BYTES>>>(
        (const __half*)Qh, (const __half*)Kh);

    rowsum_fin_kernel<<<NQ / 256, 256>>>();

    // GEMM2: out = (R . V + colsumV) / rsum   [4096 x 1024]
    hgemm2_kernel<<<dim3(DIM / BN, NQ / BM2), 256, SMEM2_BYTES>>>(
        (const __half*)R, (const __half*)Vt, out);
}

// round 9
// speedup vs baseline: 1.6099x; 1.2136x over previous
#include <cuda_runtime.h>
#include <cuda_fp16.h>
#include <cstdint>

#define NQ 4096
#define NK 8192
#define DIM 1024

// ---------------------------------------------------------------------------
// Scratch (device globals; no allocation in kernel_launch)
// ---------------------------------------------------------------------------
__device__ __half g_Qh[(size_t)NQ * DIM];     //  8 MB fp16 Q
__device__ __half g_Kh[(size_t)NK * DIM];     // 16 MB fp16 K (K-major)
__device__ __half g_Vt[(size_t)DIM * NK];     // 16 MB fp16 V^T [n][k]
__device__ __half g_R [(size_t)NQ * NK];      // 64 MB fp16 R = exp(cos)-1
__device__ float  g_qninv[NQ];
__device__ float  g_kninv[NK];
__device__ float  g_rsum[NQ];
__device__ float  g_colsum[DIM];
__device__ float  g_knpart[32][NK];           // per-dim-strip |k|^2 partials
__device__ float  g_colpart[256][DIM];        // per-key-strip colsum partials
__device__ float  g_rpart[NK / 128][NQ];      // per-n-tile row partials (GEMM1)

// ---------------------------------------------------------------------------
// PTX helpers (plain sm_103-compatible: mma.sync / ldmatrix / cp.async)
// ---------------------------------------------------------------------------
__device__ __forceinline__ uint32_t smem_u32(const void* p) {
    uint32_t a;
    asm("{ .reg .u64 t; cvta.to.shared.u64 t, %1; cvt.u32.u64 %0, t; }"
        : "=r"(a) : "l"(p));
    return a;
}
__device__ __forceinline__ void cp16(uint32_t dst, const void* src) {
    asm volatile("cp.async.cg.shared.global [%0], [%1], 16;" :: "r"(dst), "l"(src));
}
#define CP_COMMIT() asm volatile("cp.async.commit_group;" ::: "memory")
#define CP_WAIT(N)  asm volatile("cp.async.wait_group %0;" :: "n"(N) : "memory")

__device__ __forceinline__ void ldsm_x4(uint32_t (&r)[4], uint32_t addr) {
    asm volatile("ldmatrix.sync.aligned.m8n8.x4.shared.b16 {%0,%1,%2,%3}, [%4];"
        : "=r"(r[0]), "=r"(r[1]), "=r"(r[2]), "=r"(r[3]) : "r"(addr));
}
__device__ __forceinline__ void mma16816(float (&d)[4], const uint32_t (&a)[4],
                                         uint32_t b0, uint32_t b1) {
    asm volatile("mma.sync.aligned.m16n8k16.row.col.f32.f16.f16.f32 "
        "{%0,%1,%2,%3}, {%4,%5,%6,%7}, {%8,%9}, {%0,%1,%2,%3};"
        : "+f"(d[0]), "+f"(d[1]), "+f"(d[2]), "+f"(d[3])
        : "r"(a[0]), "r"(a[1]), "r"(a[2]), "r"(a[3]), "r"(b0), "r"(b1));
}

// ---------------------------------------------------------------------------
// Aux kernels (unchanged from R8 — fused single pass over K)
// ---------------------------------------------------------------------------
__global__ void convert_norm_kernel(const float* __restrict__ X,
                                    __half* __restrict__ Xh,
                                    float* __restrict__ ninv) {
    int row  = blockIdx.x * 8 + (threadIdx.x >> 5);
    int lane = threadIdx.x & 31;
    const float4* xp = (const float4*)(X + (size_t)row * DIM);
    __half2* op = (__half2*)(Xh + (size_t)row * DIM);
    float s = 0.f;
#pragma unroll
    for (int i = 0; i < 8; i++) {
        float4 v = xp[lane + 32 * i];
        s += v.x * v.x + v.y * v.y + v.z * v.z + v.w * v.w;
        op[(lane + 32 * i) * 2]     = __floats2half2_rn(v.x, v.y);
        op[(lane + 32 * i) * 2 + 1] = __floats2half2_rn(v.z, v.w);
    }
#pragma unroll
    for (int o = 16; o > 0; o >>= 1) s += __shfl_xor_sync(0xffffffffu, s, o);
    if (lane == 0) ninv[row] = rsqrtf(s);
}

__global__ void fuse_k_kernel(const float* __restrict__ K) {
    __shared__ float tile[32][33];
    int n0 = blockIdx.x * 32, k0 = blockIdx.y * 32;
    int tx = threadIdx.x, ty = threadIdx.y;
#pragma unroll
    for (int i = 0; i < 4; i++) {
        int k = k0 + ty + 8 * i;
        float v = K[(size_t)k * DIM + n0 + tx];
        g_Kh[(size_t)k * DIM + n0 + tx] = __float2half(v);
        tile[ty + 8 * i][tx] = v;
    }
    __syncthreads();
#pragma unroll
    for (int i = 0; i < 4; i++)
        g_Vt[(size_t)(n0 + ty + 8 * i) * NK + k0 + tx] =
            __float2half(tile[tx][ty + 8 * i]);
    if (ty == 0) {
        float s = 0.f;
#pragma unroll
        for (int j = 0; j < 32; j++) { float v = tile[tx][j]; s += v * v; }
        g_knpart[blockIdx.x][k0 + tx] = s;
    } else if (ty == 1) {
        float s = 0.f;
#pragma unroll
        for (int j = 0; j < 32; j++) s += tile[j][tx];
        g_colpart[blockIdx.y][n0 + tx] = s;
    }
}

__global__ void kfin_kernel() {
    int gid = blockIdx.x * 256 + threadIdx.x;
    float s = 0.f;
#pragma unroll
    for (int j = 0; j < 32; j++) s += g_knpart[j][gid];
    g_kninv[gid] = rsqrtf(s);
    if (gid < DIM) {
        float c = 0.f;
        for (int j = 0; j < 256; j++) c += g_colpart[j][gid];
        g_colsum[gid] = c;
    }
}

__global__ void rowsum_fin_kernel() {
    int m = blockIdx.x * 256 + threadIdx.x;
    float s = (float)NK;
#pragma unroll
    for (int j = 0; j < NK / 128; j++) s += g_rpart[j][m];
    g_rsum[m] = s;
}

// ---------------------------------------------------------------------------
// HMMA fp16 GEMM: 128x128x64 tile, 256 threads, 2-stage cp.async, 2 CTA/SM.
// Warp grid 4(m) x 2(n); warp tile 32m x 64n. BK=64 halves the barrier count
// vs BK=32 (16 iters GEMM1 / 128 iters GEMM2) and gives ptxas a 4-deep kk
// window to hide LDSM latency under MMA issue.
// Row pitch 144B: 8 ldsm rows step 36 words = 4 banks -> conflict-free.
//   MODE 0: A=Qh[m][k], B=Kh[n][k]; epi r=exp(acc*qninv*kninv)-1 -> g_R,
//           fused per-CTA row sums -> g_rpart[blockIdx.x][m]
//   MODE 1: A=R[m][k],  B=Vt[n][k]; epi (acc + colsum[n]) / rsum[m] -> Cout
// ---------------------------------------------------------------------------
#define BM 128
#define BN 128
#define BK 64
#define PITCHB 144                             // bytes per 64-half row
#define ST_A_BYTES (BM * PITCHB)               // 18432
#define ST_BYTES   (2 * ST_A_BYTES)            // 36864 (A + B)
#define SMEM_BYTES (2 * ST_BYTES + 1024)       // 74752 (2 stages + rp_s)

template <int MODE>
__global__ __launch_bounds__(256, 2) void hgemm_kernel(
    const __half* __restrict__ A, const __half* __restrict__ B,
    int lda, int ldb, int kdim, float* __restrict__ Cout) {
    extern __shared__ char smem[];
    const uint32_t sbase = smem_u32(smem);
    const int t = threadIdx.x;
    const int m0 = blockIdx.y * BM, n0 = blockIdx.x * BN;
    const int lane = t & 31, w = t >> 5;
    const int wm = w >> 1, wn = w & 1;          // 4 x 2 warp grid; tile 32m x 64n
    const int lrow = lane & 15, lcol = (lane >> 4) * 16;

    auto load_stage = [&](int ci, int st) {
        uint32_t sa = sbase + st * ST_BYTES;
        uint32_t sb = sa + ST_A_BYTES;
        int k0 = ci * BK;
#pragma unroll
        for (int j = 0; j < 4; j++) {           // A: 128 rows x 8 x 16B
            int idx = t + 256 * j;              // 0..1023
            int r = idx >> 3, c = idx & 7;
            cp16(sa + r * PITCHB + c * 16, A + (size_t)(m0 + r) * lda + k0 + c * 8);
        }
#pragma unroll
        for (int j = 0; j < 4; j++) {           // B: 128 rows x 8 x 16B
            int idx = t + 256 * j;
            int r = idx >> 3, c = idx & 7;
            cp16(sb + r * PITCHB + c * 16, B + (size_t)(n0 + r) * ldb + k0 + c * 8);
        }
    };

    float acc[2][8][4] = {};
    const int KT = kdim / BK;

    load_stage(0, 0); CP_COMMIT();

    for (int i = 0; i < KT; i++) {
        CP_WAIT(0);
        __syncthreads();
        if (i + 1 < KT) { load_stage(i + 1, (i + 1) & 1); CP_COMMIT(); }

        uint32_t sa = sbase + (i & 1) * ST_BYTES;
        uint32_t sb = sa + ST_A_BYTES;

#pragma unroll
        for (int kk = 0; kk < 4; kk++) {        // 4 x 16-half k-steps
            uint32_t a[2][4], bf[4][4];
#pragma unroll
            for (int mi = 0; mi < 2; mi++) {
                int row = wm * 32 + mi * 16 + lrow;
                ldsm_x4(a[mi], sa + row * PITCHB + kk * 32 + lcol);
            }
#pragma unroll
            for (int ni = 0; ni < 4; ni++) {
                int row = wn * 64 + ni * 16 + lrow;
                ldsm_x4(bf[ni], sb + row * PITCHB + kk * 32 + lcol);
            }
#pragma unroll
            for (int mi = 0; mi < 2; mi++)
#pragma unroll
                for (int ni = 0; ni < 4; ni++) {
                    mma16816(acc[mi][2 * ni],     a[mi], bf[ni][0], bf[ni][2]);
                    mma16816(acc[mi][2 * ni + 1], a[mi], bf[ni][1], bf[ni][3]);
                }
        }
    }

    // ---- Epilogue ----
    const int g = lane >> 2, q = lane & 3;
    const int rbase = m0 + wm * 32;
    const int cbase = n0 + wn * 64;

    if (MODE == 0) {
        float* rp_s = (float*)(smem + 2 * ST_BYTES);   // [2][128]
        float rs[2][2] = {};
        float kn[8][2];
#pragma unroll
        for (int nj = 0; nj < 8; nj++) {
            int c = cbase + nj * 8 + q * 2;
            kn[nj][0] = g_kninv[c]; kn[nj][1] = g_kninv[c + 1];
        }
#pragma unroll
        for (int mi = 0; mi < 2; mi++) {
            int r0 = rbase + mi * 16 + g;
            float qi0 = g_qninv[r0], qi1 = g_qninv[r0 + 8];
            __half2* d0 = (__half2*)(g_R + (size_t)r0 * NK);
            __half2* d1 = (__half2*)(g_R + (size_t)(r0 + 8) * NK);
#pragma unroll
            for (int nj = 0; nj < 8; nj++) {
                int c = cbase + nj * 8 + q * 2;
                float e00 = __expf(acc[mi][nj][0] * qi0 * kn[nj][0]) - 1.f;
                float e01 = __expf(acc[mi][nj][1] * qi0 * kn[nj][1]) - 1.f;
                float e10 = __expf(acc[mi][nj][2] * qi1 * kn[nj][0]) - 1.f;
                float e11 = __expf(acc[mi][nj][3] * qi1 * kn[nj][1]) - 1.f;
                rs[mi][0] += e00 + e01;
                rs[mi][1] += e10 + e11;
                d0[c >> 1] = __floats2half2_rn(e00, e01);
                d1[c >> 1] = __floats2half2_rn(e10, e11);
            }
        }
#pragma unroll
        for (int mi = 0; mi < 2; mi++)
#pragma unroll
            for (int h = 0; h < 2; h++) {
                float v = rs[mi][h];
                v += __shfl_xor_sync(0xffffffffu, v, 1);
                v += __shfl_xor_sync(0xffffffffu, v, 2);
                rs[mi][h] = v;
            }
        if (q == 0) {
#pragma unroll
            for (int mi = 0; mi < 2; mi++)
#pragma unroll
                for (int h = 0; h < 2; h++)
                    rp_s[wn * 128 + wm * 32 + mi * 16 + h * 8 + g] = rs[mi][h];
        }
        __syncthreads();
        if (t < 128)
            g_rpart[blockIdx.x][m0 + t] = rp_s[t] + rp_s[128 + t];
    } else {
#pragma unroll
        for (int mi = 0; mi < 2; mi++) {
            int r0 = rbase + mi * 16 + g;
            float ri0 = 1.0f / g_rsum[r0], ri1 = 1.0f / g_rsum[r0 + 8];
            float* d0 = Cout + (size_t)r0 * DIM;
            float* d1 = Cout + (size_t)(r0 + 8) * DIM;
#pragma unroll
            for (int nj = 0; nj < 8; nj++) {
                int c = cbase + nj * 8 + q * 2;
                float cs0 = g_colsum[c], cs1 = g_colsum[c + 1];
                *(float2*)(d0 + c) = make_float2((acc[mi][nj][0] + cs0) * ri0,
                                                 (acc[mi][nj][1] + cs1) * ri0);
                *(float2*)(d1 + c) = make_float2((acc[mi][nj][2] + cs0) * ri1,
                                                 (acc[mi][nj][3] + cs1) * ri1);
            }
        }
    }
}

// ---------------------------------------------------------------------------
// Launch
// ---------------------------------------------------------------------------
extern "C" void kernel_launch(void* const* d_in, const int* in_sizes, int n_in,
                              void* d_out, int out_size) {
    const float* Q = (const float*)d_in[0];   // [4096, 1024]
    const float* K = (const float*)d_in[1];   // [8192, 1024] (keys == values)
    float* out = (float*)d_out;               // [4096, 1024]
    (void)in_sizes; (void)n_in; (void)out_size;

    void *Qh, *Kh, *Vt, *R, *qn;
    cudaGetSymbolAddress(&Qh, g_Qh);
    cudaGetSymbolAddress(&Kh, g_Kh);
    cudaGetSymbolAddress(&Vt, g_Vt);
    cudaGetSymbolAddress(&R,  g_R);
    cudaGetSymbolAddress(&qn, g_qninv);

    cudaFuncSetAttribute(hgemm_kernel<0>, cudaFuncAttributeMaxDynamicSharedMemorySize, SMEM_BYTES);
    cudaFuncSetAttribute(hgemm_kernel<1>, cudaFuncAttributeMaxDynamicSharedMemorySize, SMEM_BYTES);

    convert_norm_kernel<<<NQ / 8, 256>>>(Q, (__half*)Qh, (float*)qn);
    fuse_k_kernel<<<dim3(DIM / 32, NK / 32), dim3(32, 8)>>>(K);
    kfin_kernel<<<NK / 256, 256>>>();

    // GEMM1: R = exp(cos(Q,K)) - 1   [4096 x 8192] (+ fused row partials)
    hgemm_kernel<0><<<dim3(NK / BN, NQ / BM), 256, SMEM_BYTES>>>(
        (const __half*)Qh, (const __half*)Kh, DIM, DIM, DIM, nullptr);

    rowsum_fin_kernel<<<NQ / 256, 256>>>();

    // GEMM2: out = (R . V + colsumV) / rsum   [4096 x 1024]
    hgemm_kernel<1><<<dim3(DIM / BN, NQ / BM), 256, SMEM_BYTES>>>(
        (const __half*)R, (const __half*)Vt, NK, NK, NK, out);
}

// round 10
// speedup vs baseline: 1.6163x; 1.0040x over previous
#include <cuda_runtime.h>
#include <cuda_fp16.h>
#include <cstdint>

#define NQ 4096
#define NK 8192
#define DIM 1024

// ---------------------------------------------------------------------------
// Scratch (device globals; no allocation in kernel_launch)
// ---------------------------------------------------------------------------
__device__ __half g_Qh[(size_t)NQ * DIM];     //  8 MB fp16 Q
__device__ __half g_Kh[(size_t)NK * DIM];     // 16 MB fp16 K (K-major)
__device__ __half g_Vt[(size_t)DIM * NK];     // 16 MB fp16 V^T [n][k]
__device__ __half g_R [(size_t)NQ * NK];      // 64 MB fp16 R = exp(cos)-1
__device__ float  g_qninv[NQ];
__device__ float  g_kninv[NK];
__device__ float  g_rsum[NQ];
__device__ float  g_colsum[DIM];
__device__ float  g_knpart[32][NK];           // per-dim-strip |k|^2 partials
__device__ float  g_colpart[256][DIM];        // per-key-strip colsum partials
__device__ float  g_rpart[NK / 128][NQ];      // per-n-tile row partials (GEMM1)

// ---------------------------------------------------------------------------
// PTX helpers (plain sm_103-compatible: mma.sync / ldmatrix / cp.async)
// ---------------------------------------------------------------------------
__device__ __forceinline__ uint32_t smem_u32(const void* p) {
    uint32_t a;
    asm("{ .reg .u64 t; cvta.to.shared.u64 t, %1; cvt.u32.u64 %0, t; }"
        : "=r"(a) : "l"(p));
    return a;
}
__device__ __forceinline__ void cp16(uint32_t dst, const void* src) {
    asm volatile("cp.async.cg.shared.global [%0], [%1], 16;" :: "r"(dst), "l"(src));
}
#define CP_COMMIT() asm volatile("cp.async.commit_group;" ::: "memory")
#define CP_WAIT(N)  asm volatile("cp.async.wait_group %0;" :: "n"(N) : "memory")

__device__ __forceinline__ void ldsm_x4(uint32_t (&r)[4], uint32_t addr) {
    asm volatile("ldmatrix.sync.aligned.m8n8.x4.shared.b16 {%0,%1,%2,%3}, [%4];"
        : "=r"(r[0]), "=r"(r[1]), "=r"(r[2]), "=r"(r[3]) : "r"(addr));
}
__device__ __forceinline__ void mma16816(float (&d)[4], const uint32_t (&a)[4],
                                         uint32_t b0, uint32_t b1) {
    asm volatile("mma.sync.aligned.m16n8k16.row.col.f32.f16.f16.f32 "
        "{%0,%1,%2,%3}, {%4,%5,%6,%7}, {%8,%9}, {%0,%1,%2,%3};"
        : "+f"(d[0]), "+f"(d[1]), "+f"(d[2]), "+f"(d[3])
        : "r"(a[0]), "r"(a[1]), "r"(a[2]), "r"(a[3]), "r"(b0), "r"(b1));
}

// ---------------------------------------------------------------------------
// Aux kernels (fused single pass over K; unchanged)
// ---------------------------------------------------------------------------
__global__ void convert_norm_kernel(const float* __restrict__ X,
                                    __half* __restrict__ Xh,
                                    float* __restrict__ ninv) {
    int row  = blockIdx.x * 8 + (threadIdx.x >> 5);
    int lane = threadIdx.x & 31;
    const float4* xp = (const float4*)(X + (size_t)row * DIM);
    __half2* op = (__half2*)(Xh + (size_t)row * DIM);
    float s = 0.f;
#pragma unroll
    for (int i = 0; i < 8; i++) {
        float4 v = xp[lane + 32 * i];
        s += v.x * v.x + v.y * v.y + v.z * v.z + v.w * v.w;
        op[(lane + 32 * i) * 2]     = __floats2half2_rn(v.x, v.y);
        op[(lane + 32 * i) * 2 + 1] = __floats2half2_rn(v.z, v.w);
    }
#pragma unroll
    for (int o = 16; o > 0; o >>= 1) s += __shfl_xor_sync(0xffffffffu, s, o);
    if (lane == 0) ninv[row] = rsqrtf(s);
}

__global__ void fuse_k_kernel(const float* __restrict__ K) {
    __shared__ float tile[32][33];
    int n0 = blockIdx.x * 32, k0 = blockIdx.y * 32;
    int tx = threadIdx.x, ty = threadIdx.y;
#pragma unroll
    for (int i = 0; i < 4; i++) {
        int k = k0 + ty + 8 * i;
        float v = K[(size_t)k * DIM + n0 + tx];
        g_Kh[(size_t)k * DIM + n0 + tx] = __float2half(v);
        tile[ty + 8 * i][tx] = v;
    }
    __syncthreads();
#pragma unroll
    for (int i = 0; i < 4; i++)
        g_Vt[(size_t)(n0 + ty + 8 * i) * NK + k0 + tx] =
            __float2half(tile[tx][ty + 8 * i]);
    if (ty == 0) {
        float s = 0.f;
#pragma unroll
        for (int j = 0; j < 32; j++) { float v = tile[tx][j]; s += v * v; }
        g_knpart[blockIdx.x][k0 + tx] = s;
    } else if (ty == 1) {
        float s = 0.f;
#pragma unroll
        for (int j = 0; j < 32; j++) s += tile[j][tx];
        g_colpart[blockIdx.y][n0 + tx] = s;
    }
}

__global__ void kfin_kernel() {
    int gid = blockIdx.x * 256 + threadIdx.x;
    float s = 0.f;
#pragma unroll
    for (int j = 0; j < 32; j++) s += g_knpart[j][gid];
    g_kninv[gid] = rsqrtf(s);
    if (gid < DIM) {
        float c = 0.f;
        for (int j = 0; j < 256; j++) c += g_colpart[j][gid];
        g_colsum[gid] = c;
    }
}

__global__ void rowsum_fin_kernel() {
    int m = blockIdx.x * 256 + threadIdx.x;
    float s = (float)NK;
#pragma unroll
    for (int j = 0; j < NK / 128; j++) s += g_rpart[j][m];
    g_rsum[m] = s;
}

// ---------------------------------------------------------------------------
// HMMA fp16 GEMM: 128x128x64 tile, 256 threads, 3-stage cp.async, 2 CTA/SM.
// Warp grid 4(m) x 2(n); warp tile 32m x 64n. CP_WAIT(1) keeps one load
// group in flight (two iterations of load lead). Global addresses are
// precomputed per-thread row pointers (one IMAD per stage, not full chains).
// Row pitch 144B keeps ldmatrix conflict-free.
//   MODE 0: A=Qh[m][k], B=Kh[n][k]; epi r=exp(acc*qninv*kninv)-1 -> g_R,
//           fused per-CTA row sums -> g_rpart[blockIdx.x][m]
//   MODE 1: A=R[m][k],  B=Vt[n][k]; epi (acc + colsum[n]) / rsum[m] -> Cout
// ---------------------------------------------------------------------------
#define BM 128
#define BN 128
#define BK 64
#define STAGES 3
#define PITCHB 144                             // bytes per 64-half row
#define ST_A_BYTES (BM * PITCHB)               // 18432
#define ST_BYTES   (2 * ST_A_BYTES)            // 36864 (A + B)
#define SMEM_BYTES (STAGES * ST_BYTES + 1024)  // 111616 (stages + rp_s)

template <int MODE>
__global__ __launch_bounds__(256, 2) void hgemm_kernel(
    const __half* __restrict__ A, const __half* __restrict__ B,
    int lda, int ldb, int kdim, float* __restrict__ Cout) {
    extern __shared__ char smem[];
    const uint32_t sbase = smem_u32(smem);
    const int t = threadIdx.x;
    const int m0 = blockIdx.y * BM, n0 = blockIdx.x * BN;
    const int lane = t & 31, w = t >> 5;
    const int wm = w >> 1, wn = w & 1;          // 4 x 2 warp grid; tile 32m x 64n
    const int lrow = lane & 15, lcol = (lane >> 4) * 16;

    // Per-thread load geometry: 128 rows x 8 chunks(16B); 256 threads do 4
    // (row, chunk) pairs per operand per stage. Precompute global pointers.
    const int r_ld = t >> 3;                    // 0..31 base row
    const int c_ld = t & 7;                     // 16B chunk
    const __half* aptr[4];
    const __half* bptr[4];
    uint32_t s_off[4];
#pragma unroll
    for (int j = 0; j < 4; j++) {
        int r = r_ld + 32 * j;
        aptr[j] = A + (size_t)(m0 + r) * lda + c_ld * 8;
        bptr[j] = B + (size_t)(n0 + r) * ldb + c_ld * 8;
        s_off[j] = r * PITCHB + c_ld * 16;
    }

    auto load_stage = [&](int ci, int st) {
        uint32_t sa = sbase + st * ST_BYTES;
        uint32_t sb = sa + ST_A_BYTES;
        int k0 = ci * BK;
#pragma unroll
        for (int j = 0; j < 4; j++) {
            cp16(sa + s_off[j], aptr[j] + k0);
            cp16(sb + s_off[j], bptr[j] + k0);
        }
    };

    float acc[2][8][4] = {};
    const int KT = kdim / BK;

    load_stage(0, 0); CP_COMMIT();
    load_stage(1, 1); CP_COMMIT();

    for (int i = 0; i < KT; i++) {
        CP_WAIT(1);
        __syncthreads();
        if (i + 2 < KT) { load_stage(i + 2, (i + 2) % STAGES); }
        CP_COMMIT();

        uint32_t sa = sbase + (i % STAGES) * ST_BYTES;
        uint32_t sb = sa + ST_A_BYTES;

#pragma unroll
        for (int kk = 0; kk < 4; kk++) {        // 4 x 16-half k-steps
            uint32_t a[2][4], bf[4][4];
#pragma unroll
            for (int mi = 0; mi < 2; mi++) {
                int row = wm * 32 + mi * 16 + lrow;
                ldsm_x4(a[mi], sa + row * PITCHB + kk * 32 + lcol);
            }
#pragma unroll
            for (int ni = 0; ni < 4; ni++) {
                int row = wn * 64 + ni * 16 + lrow;
                ldsm_x4(bf[ni], sb + row * PITCHB + kk * 32 + lcol);
            }
#pragma unroll
            for (int mi = 0; mi < 2; mi++)
#pragma unroll
                for (int ni = 0; ni < 4; ni++) {
                    mma16816(acc[mi][2 * ni],     a[mi], bf[ni][0], bf[ni][2]);
                    mma16816(acc[mi][2 * ni + 1], a[mi], bf[ni][1], bf[ni][3]);
                }
        }
    }

    // ---- Epilogue ----
    const int g = lane >> 2, q = lane & 3;
    const int rbase = m0 + wm * 32;
    const int cbase = n0 + wn * 64;

    if (MODE == 0) {
        float* rp_s = (float*)(smem + STAGES * ST_BYTES);   // [2][128]
        float rs[2][2] = {};
        float kn[8][2];
#pragma unroll
        for (int nj = 0; nj < 8; nj++) {
            int c = cbase + nj * 8 + q * 2;
            kn[nj][0] = g_kninv[c]; kn[nj][1] = g_kninv[c + 1];
        }
#pragma unroll
        for (int mi = 0; mi < 2; mi++) {
            int r0 = rbase + mi * 16 + g;
            float qi0 = g_qninv[r0], qi1 = g_qninv[r0 + 8];
            __half2* d0 = (__half2*)(g_R + (size_t)r0 * NK);
            __half2* d1 = (__half2*)(g_R + (size_t)(r0 + 8) * NK);
#pragma unroll
            for (int nj = 0; nj < 8; nj++) {
                int c = cbase + nj * 8 + q * 2;
                float e00 = __expf(acc[mi][nj][0] * qi0 * kn[nj][0]) - 1.f;
                float e01 = __expf(acc[mi][nj][1] * qi0 * kn[nj][1]) - 1.f;
                float e10 = __expf(acc[mi][nj][2] * qi1 * kn[nj][0]) - 1.f;
                float e11 = __expf(acc[mi][nj][3] * qi1 * kn[nj][1]) - 1.f;
                rs[mi][0] += e00 + e01;
                rs[mi][1] += e10 + e11;
                d0[c >> 1] = __floats2half2_rn(e00, e01);
                d1[c >> 1] = __floats2half2_rn(e10, e11);
            }
        }
#pragma unroll
        for (int mi = 0; mi < 2; mi++)
#pragma unroll
            for (int h = 0; h < 2; h++) {
                float v = rs[mi][h];
                v += __shfl_xor_sync(0xffffffffu, v, 1);
                v += __shfl_xor_sync(0xffffffffu, v, 2);
                rs[mi][h] = v;
            }
        if (q == 0) {
#pragma unroll
            for (int mi = 0; mi < 2; mi++)
#pragma unroll
                for (int h = 0; h < 2; h++)
                    rp_s[wn * 128 + wm * 32 + mi * 16 + h * 8 + g] = rs[mi][h];
        }
        __syncthreads();
        if (t < 128)
            g_rpart[blockIdx.x][m0 + t] = rp_s[t] + rp_s[128 + t];
    } else {
#pragma unroll
        for (int mi = 0; mi < 2; mi++) {
            int r0 = rbase + mi * 16 + g;
            float ri0 = 1.0f / g_rsum[r0], ri1 = 1.0f / g_rsum[r0 + 8];
            float* d0 = Cout + (size_t)r0 * DIM;
            float* d1 = Cout + (size_t)(r0 + 8) * DIM;
#pragma unroll
            for (int nj = 0; nj < 8; nj++) {
                int c = cbase + nj * 8 + q * 2;
                float cs0 = g_colsum[c], cs1 = g_colsum[c + 1];
                *(float2*)(d0 + c) = make_float2((acc[mi][nj][0] + cs0) * ri0,
                                                 (acc[mi][nj][1] + cs1) * ri0);
                *(float2*)(d1 + c) = make_float2((acc[mi][nj][2] + cs0) * ri1,
                                                 (acc[mi][nj][3] + cs1) * ri1);
            }
        }
    }
}

// ---------------------------------------------------------------------------
// Launch
// ---------------------------------------------------------------------------
extern "C" void kernel_launch(void* const* d_in, const int* in_sizes, int n_in,
                              void* d_out, int out_size) {
    const float* Q = (const float*)d_in[0];   // [4096, 1024]
    const float* K = (const float*)d_in[1];   // [8192, 1024] (keys == values)
    float* out = (float*)d_out;               // [4096, 1024]
    (void)in_sizes; (void)n_in; (void)out_size;

    void *Qh, *Kh, *Vt, *R, *qn;
    cudaGetSymbolAddress(&Qh, g_Qh);
    cudaGetSymbolAddress(&Kh, g_Kh);
    cudaGetSymbolAddress(&Vt, g_Vt);
    cudaGetSymbolAddress(&R,  g_R);
    cudaGetSymbolAddress(&qn, g_qninv);

    cudaFuncSetAttribute(hgemm_kernel<0>, cudaFuncAttributeMaxDynamicSharedMemorySize, SMEM_BYTES);
    cudaFuncSetAttribute(hgemm_kernel<1>, cudaFuncAttributeMaxDynamicSharedMemorySize, SMEM_BYTES);

    convert_norm_kernel<<<NQ / 8, 256>>>(Q, (__half*)Qh, (float*)qn);
    fuse_k_kernel<<<dim3(DIM / 32, NK / 32), dim3(32, 8)>>>(K);
    kfin_kernel<<<NK / 256, 256>>>();

    // GEMM1: R = exp(cos(Q,K)) - 1   [4096 x 8192] (+ fused row partials)
    hgemm_kernel<0><<<dim3(NK / BN, NQ / BM), 256, SMEM_BYTES>>>(
        (const __half*)Qh, (const __half*)Kh, DIM, DIM, DIM, nullptr);

    rowsum_fin_kernel<<<NQ / 256, 256>>>();

    // GEMM2: out = (R . V + colsumV) / rsum   [4096 x 1024]
    hgemm_kernel<1><<<dim3(DIM / BN, NQ / BM), 256, SMEM_BYTES>>>(
        (const __half*)R, (const __half*)Vt, NK, NK, NK, out);
}